// round 1
// baseline (speedup 1.0000x reference)
#include <cuda_runtime.h>
#include <cstdio>

#define NP 200000
#define NH 500000
#define NG 20000
#define NE_T 800000
#define NE_E 1000000
#define NE_H 500000
#define HD 128

// -------- scratch (static device allocations; no cudaMalloc anywhere) --------
__device__ float g_P0[(size_t)NP * HD];            // 102.4 MB
__device__ float g_P1[(size_t)NP * HD];            // 102.4 MB
__device__ float g_Hf[(size_t)NH * HD];            // 256 MB
__device__ float g_AGG[3ULL * NP * HD];            // 307 MB  [t | e | h]
__device__ float g_ICNT[3 * NP];                   // inverse counts per edge type
__device__ float g_WrS[2 * HD * HD];               // Wr0+Wr1+Wr2 per layer
__device__ float g_bS[2 * HD];                     // b0+b1+b2 per layer
__device__ float g_GC[NG];                         // graph counts

// ------------------------------- utility ------------------------------------
__global__ void zero_buf(float* p, size_t n) {
    for (size_t i = (size_t)blockIdx.x * blockDim.x + threadIdx.x; i < n;
         i += (size_t)gridDim.x * blockDim.x)
        p[i] = 0.0f;
}

__global__ void count_k(const int* __restrict__ edge, int ne, float* __restrict__ cnt) {
    int i = blockIdx.x * blockDim.x + threadIdx.x;
    if (i < ne) atomicAdd(&cnt[edge[ne + i]], 1.0f);
}

__global__ void invert_k(float* c, int n) {
    int i = blockIdx.x * blockDim.x + threadIdx.x;
    if (i < n) c[i] = 1.0f / fmaxf(c[i], 1.0f);
}

// Combine the three Wr / b across edge types (per layer)
__global__ void wrsum_k(const float* __restrict__ Wr, const float* __restrict__ b,
                        float* __restrict__ WrS, float* __restrict__ bS) {
    int i = blockIdx.x * blockDim.x + threadIdx.x;
    if (i < 2 * HD * HD) {
        int l = i / (HD * HD);
        int ok = i - l * HD * HD;
        WrS[i] = Wr[(l * 3 + 0) * HD * HD + ok] + Wr[(l * 3 + 1) * HD * HD + ok] +
                 Wr[(l * 3 + 2) * HD * HD + ok];
    }
    if (i < 2 * HD) {
        int l = i / HD, o = i - l * HD;
        bS[i] = b[(l * 3 + 0) * HD + o] + b[(l * 3 + 1) * HD + o] + b[(l * 3 + 2) * HD + o];
    }
}

// --------------------------- feature encoders --------------------------------
// p = concat(cont5, 5 x emb16) @ Wp.T + bp        (K = 85)
__global__ __launch_bounds__(128) void enc_p(const float* __restrict__ xp,
                                             const float* __restrict__ embp,
                                             const float* __restrict__ Wp,
                                             const float* __restrict__ bp,
                                             float* __restrict__ out) {
    __shared__ float f[8][85];
    int r0 = blockIdx.x * 8;
    int tid = threadIdx.x;
    for (int idx = tid; idx < 8 * 85; idx += 128) {
        int r = idx / 85, k = idx - r * 85;
        const float* x = xp + (size_t)(r0 + r) * 10;
        float v;
        if (k < 5) {
            v = x[k == 0 ? 0 : k + 5];  // cols {0,6,7,8,9}
        } else {
            int j = (k - 5) >> 4, e = (k - 5) & 15;
            int ci = (int)x[1 + j];
            ci = min(max(ci, 0), 199);
            v = embp[((size_t)j * 200 + ci) * 16 + e];
        }
        f[r][k] = v;
    }
    __syncthreads();
    float acc[8];
#pragma unroll
    for (int r = 0; r < 8; r++) acc[r] = bp[tid];
    const float* w = Wp + tid * 85;
    for (int k = 0; k < 85; k++) {
        float wk = __ldg(w + k);
#pragma unroll
        for (int r = 0; r < 8; r++) acc[r] += f[r][k] * wk;
    }
#pragma unroll
    for (int r = 0; r < 8; r++) out[(size_t)(r0 + r) * HD + tid] = acc[r];
}

// hist = concat(cont6, emb16, emb4) @ Wh.T + bh   (K = 26)
__global__ __launch_bounds__(128) void enc_h(const float* __restrict__ xh,
                                             const float* __restrict__ e0,
                                             const float* __restrict__ e3,
                                             const float* __restrict__ Wh,
                                             const float* __restrict__ bh,
                                             float* __restrict__ out) {
    __shared__ float f[16][26];
    int r0 = blockIdx.x * 16;
    int tid = threadIdx.x;
    for (int idx = tid; idx < 16 * 26; idx += 128) {
        int r = idx / 26, k = idx - r * 26;
        const float* x = xh + (size_t)(r0 + r) * 8;
        float v;
        if (k < 6) {
            // cols {1,2,4,5,6,7}
            v = x[k < 2 ? k + 1 : k + 2];
        } else if (k < 22) {
            int ci = (int)x[0];
            ci = min(max(ci, 0), 1999);
            v = e0[ci * 16 + (k - 6)];
        } else {
            int ci = (int)x[3];
            ci = min(max(ci, 0), 9);
            v = e3[ci * 4 + (k - 22)];
        }
        f[r][k] = v;
    }
    __syncthreads();
    float acc[16];
#pragma unroll
    for (int r = 0; r < 16; r++) acc[r] = bh[tid];
    const float* w = Wh + tid * 26;
    for (int k = 0; k < 26; k++) {
        float wk = __ldg(w + k);
#pragma unroll
        for (int r = 0; r < 16; r++) acc[r] += f[r][k] * wk;
    }
#pragma unroll
    for (int r = 0; r < 16; r++) out[(size_t)(r0 + r) * HD + tid] = acc[r];
}

// ------------------------------ aggregation ----------------------------------
// One warp per edge: gather 512B src row, scatter-atomic into dst row.
__global__ __launch_bounds__(256) void agg_k(const float* __restrict__ src_feat,
                                             const int* __restrict__ edge, int ne,
                                             float* __restrict__ agg) {
    int w = (blockIdx.x * blockDim.x + threadIdx.x) >> 5;
    int lane = threadIdx.x & 31;
    if (w >= ne) return;
    int s = edge[w];
    int d = edge[ne + w];
    const float4* srow = (const float4*)(src_feat + (size_t)s * HD);
    float4 v = srow[lane];
    float* drow = agg + (size_t)d * HD + lane * 4;
    atomicAdd(drow + 0, v.x);
    atomicAdd(drow + 1, v.y);
    atomicAdd(drow + 2, v.z);
    atomicAdd(drow + 3, v.w);
}

// ------------------------------- SAGE GEMM -----------------------------------
// C[n][o] = relu( [agg_t*ic | agg_e*ic | agg_h*ic | P](n, 512) @ Wbig(o, 512).T + bS[o] )
// Tiled fp32: BM=64, BN=128, BK=32, 256 threads, 4x8 per-thread microtile.
__global__ __launch_bounds__(256) void sage_gemm(const float* __restrict__ agg,
                                                 const float* __restrict__ icnt,
                                                 const float* __restrict__ P,
                                                 const float* __restrict__ Wl,   // [3][128][128]
                                                 const float* __restrict__ WrS,  // [128][128]
                                                 const float* __restrict__ bS,   // [128]
                                                 float* __restrict__ out) {
    __shared__ float Xs[64][33];
    __shared__ float Ws[128][33];
    int tid = threadIdx.x;
    int tr = tid >> 4;   // 0..15 -> rows tr*4..tr*4+3
    int tc = tid & 15;   // 0..15 -> cols tc*8..tc*8+7
    int rowBase = blockIdx.x * 64;

    float acc[4][8];
#pragma unroll
    for (int i = 0; i < 4; i++)
#pragma unroll
        for (int j = 0; j < 8; j++) acc[i][j] = 0.0f;

    for (int kc = 0; kc < 16; kc++) {
        int part = kc >> 2;
        int klb = (kc & 3) * 32;
#pragma unroll
        for (int t = 0; t < 8; t++) {
            int idx = tid + t * 256;
            int r = idx >> 5, kk = idx & 31;
            int row = rowBase + r;
            float v;
            if (part < 3)
                v = agg[((size_t)part * NP + row) * HD + klb + kk] * icnt[part * NP + row];
            else
                v = P[(size_t)row * HD + klb + kk];
            Xs[r][kk] = v;
        }
#pragma unroll
        for (int t = 0; t < 16; t++) {
            int idx = tid + t * 256;
            int o = idx >> 5, kk = idx & 31;
            float wv = (part < 3) ? Wl[((size_t)part * HD + o) * HD + klb + kk]
                                  : WrS[(size_t)o * HD + klb + kk];
            Ws[o][kk] = wv;
        }
        __syncthreads();
#pragma unroll
        for (int kk = 0; kk < 32; kk++) {
            float xr[4], wr[8];
#pragma unroll
            for (int i = 0; i < 4; i++) xr[i] = Xs[tr * 4 + i][kk];
#pragma unroll
            for (int j = 0; j < 8; j++) wr[j] = Ws[tc * 8 + j][kk];
#pragma unroll
            for (int i = 0; i < 4; i++)
#pragma unroll
                for (int j = 0; j < 8; j++) acc[i][j] += xr[i] * wr[j];
        }
        __syncthreads();
    }
#pragma unroll
    for (int i = 0; i < 4; i++) {
        int row = rowBase + tr * 4 + i;
#pragma unroll
        for (int j = 0; j < 8; j++) {
            float v = acc[i][j] + bS[tc * 8 + j];
            out[(size_t)row * HD + tc * 8 + j] = fmaxf(v, 0.0f);
        }
    }
}

// ------------------------------ pooling/head ---------------------------------
// out[g] = mean_{i in g}( dot(p_i, Wc) ) + bc   (linearity of the head)
__global__ __launch_bounds__(256) void pool_k(const float* __restrict__ P,
                                              const int* __restrict__ batch,
                                              const float* __restrict__ Wc,
                                              float* __restrict__ out, float* __restrict__ gc) {
    int row = (blockIdx.x * blockDim.x + threadIdx.x) >> 5;
    int lane = threadIdx.x & 31;
    if (row >= NP) return;
    const float4* pr = (const float4*)(P + (size_t)row * HD);
    const float4* wr = (const float4*)Wc;
    float4 a = pr[lane], b = wr[lane];
    float s = a.x * b.x + a.y * b.y + a.z * b.z + a.w * b.w;
#pragma unroll
    for (int o = 16; o; o >>= 1) s += __shfl_xor_sync(0xFFFFFFFFu, s, o);
    if (lane == 0) {
        int g = batch[row];
        atomicAdd(&out[g], s);
        atomicAdd(&gc[g], 1.0f);
    }
}

__global__ void fin_k(float* out, const float* gc, const float* __restrict__ bc) {
    int g = blockIdx.x * blockDim.x + threadIdx.x;
    if (g < NG) out[g] = out[g] / fmaxf(gc[g], 1.0f) + bc[0];
}

// -------------------------------- launcher -----------------------------------
extern "C" void kernel_launch(void* const* d_in, const int* in_sizes, int n_in,
                              void* d_out, int out_size) {
    const float* x_player = (const float*)d_in[0];
    const float* x_hist   = (const float*)d_in[1];
    const int*   e_t      = (const int*)d_in[2];
    const int*   e_e      = (const int*)d_in[3];
    const int*   e_h      = (const int*)d_in[4];
    const int*   batch    = (const int*)d_in[5];
    const float* emb_p    = (const float*)d_in[6];
    const float* emb_h0   = (const float*)d_in[7];
    const float* emb_h3   = (const float*)d_in[8];
    const float* Wp       = (const float*)d_in[9];
    const float* bp       = (const float*)d_in[10];
    const float* Wh       = (const float*)d_in[11];
    const float* bh       = (const float*)d_in[12];
    const float* sWl      = (const float*)d_in[13];
    const float* sb       = (const float*)d_in[14];
    const float* sWr      = (const float*)d_in[15];
    const float* Wc       = (const float*)d_in[16];
    const float* bc       = (const float*)d_in[17];
    float* out = (float*)d_out;

    float *P0, *P1, *Hf, *AGG, *ICNT, *WrS, *bS, *GC;
    cudaGetSymbolAddress((void**)&P0, g_P0);
    cudaGetSymbolAddress((void**)&P1, g_P1);
    cudaGetSymbolAddress((void**)&Hf, g_Hf);
    cudaGetSymbolAddress((void**)&AGG, g_AGG);
    cudaGetSymbolAddress((void**)&ICNT, g_ICNT);
    cudaGetSymbolAddress((void**)&WrS, g_WrS);
    cudaGetSymbolAddress((void**)&bS, g_bS);
    cudaGetSymbolAddress((void**)&GC, g_GC);

    const size_t NPHD = (size_t)NP * HD;

    // counts (fixed across layers)
    zero_buf<<<1024, 256>>>(ICNT, 3 * NP);
    count_k<<<(NE_T + 255) / 256, 256>>>(e_t, NE_T, ICNT);
    count_k<<<(NE_E + 255) / 256, 256>>>(e_e, NE_E, ICNT + NP);
    count_k<<<(NE_H + 255) / 256, 256>>>(e_h, NE_H, ICNT + 2 * NP);
    invert_k<<<(3 * NP + 255) / 256, 256>>>(ICNT, 3 * NP);

    // combined Wr / b
    wrsum_k<<<(2 * HD * HD + 255) / 256, 256>>>(sWr, sb, WrS, bS);

    // encoders
    enc_p<<<NP / 8, 128>>>(x_player, emb_p, Wp, bp, P0);
    enc_h<<<NH / 16, 128>>>(x_hist, emb_h0, emb_h3, Wh, bh, Hf);

    // hist aggregation (layer-invariant: hist features never update)
    zero_buf<<<4096, 256>>>(AGG + 2 * NPHD, NPHD);
    agg_k<<<NE_H / 8, 256>>>(Hf, e_h, NE_H, AGG + 2 * NPHD);

    // ---- layer 0 ----
    zero_buf<<<8192, 256>>>(AGG, 2 * NPHD);
    agg_k<<<NE_T / 8, 256>>>(P0, e_t, NE_T, AGG);
    agg_k<<<NE_E / 8, 256>>>(P0, e_e, NE_E, AGG + NPHD);
    sage_gemm<<<NP / 64, 256>>>(AGG, ICNT, P0, sWl, WrS, bS, P1);

    // ---- layer 1 ----
    zero_buf<<<8192, 256>>>(AGG, 2 * NPHD);
    agg_k<<<NE_T / 8, 256>>>(P1, e_t, NE_T, AGG);
    agg_k<<<NE_E / 8, 256>>>(P1, e_e, NE_E, AGG + NPHD);
    sage_gemm<<<NP / 64, 256>>>(AGG, ICNT, P1, sWl + 3 * HD * HD, WrS + HD * HD, bS + HD, P0);

    // pooling + head
    zero_buf<<<(NG + 255) / 256, 256>>>(out, NG);
    zero_buf<<<(NG + 255) / 256, 256>>>(GC, NG);
    pool_k<<<NP * 32 / 256, 256>>>(P0, batch, Wc, out, GC);
    fin_k<<<(NG + 255) / 256, 256>>>(out, GC, bc);
}

// round 3
// speedup vs baseline: 2.6407x; 2.6407x over previous
#include <cuda_runtime.h>
#include <cstdint>

#define NP 200000
#define NH 500000
#define NG 20000
#define NE_T 800000
#define NE_E 1000000
#define NE_H 500000
#define NE_ALL (NE_T + NE_E + NE_H)
#define HD 128
#define SCAN_N (3 * NP)
#define SCAN_BLOCKS ((SCAN_N + 2047) / 2048)

// -------- static scratch (no allocations anywhere) --------
__device__ float g_P0[(size_t)NP * HD];      // 102.4 MB
__device__ float g_P1[(size_t)NP * HD];      // 102.4 MB
__device__ float g_Hf[(size_t)NH * HD];      // 256 MB
__device__ float g_X[(size_t)NP * 384];      // 307 MB  [aggT | aggE | aggH]
__device__ float g_Wb[2 * 512 * HD];         // fused weights [layer][k][o]
__device__ float g_bSum[2 * HD];
__device__ float g_GC[NG];
__device__ int g_cnt[SCAN_N];
__device__ int g_cur[SCAN_N];
__device__ int g_offs[SCAN_N];
__device__ int g_bsum[SCAN_BLOCKS];
__device__ int g_sorted[NE_ALL];

// ------------------------------- utility ------------------------------------
__global__ void zero_buf(float* p, size_t n) {
    for (size_t i = (size_t)blockIdx.x * blockDim.x + threadIdx.x; i < n;
         i += (size_t)gridDim.x * blockDim.x)
        p[i] = 0.0f;
}

__global__ void counti_k(const int* __restrict__ edge, int ne, int* __restrict__ cnt) {
    int i = blockIdx.x * blockDim.x + threadIdx.x;
    if (i < ne) atomicAdd(&cnt[edge[ne + i]], 1);
}

// ------------------------------- scan (exclusive) ----------------------------
__global__ void scan1(const int* __restrict__ in, int* __restrict__ out, int* __restrict__ bsum) {
    __shared__ int ts[256];
    int base = blockIdx.x * 2048 + threadIdx.x * 8;
    int v[8];
    int s = 0;
#pragma unroll
    for (int j = 0; j < 8; j++) {
        int idx = base + j;
        v[j] = (idx < SCAN_N) ? in[idx] : 0;
        s += v[j];
    }
    ts[threadIdx.x] = s;
    __syncthreads();
    for (int off = 1; off < 256; off <<= 1) {
        int t = (threadIdx.x >= off) ? ts[threadIdx.x - off] : 0;
        __syncthreads();
        ts[threadIdx.x] += t;
        __syncthreads();
    }
    int run = ts[threadIdx.x] - s;  // exclusive
    if (threadIdx.x == 255) bsum[blockIdx.x] = ts[255];
#pragma unroll
    for (int j = 0; j < 8; j++) {
        int idx = base + j;
        if (idx < SCAN_N) out[idx] = run;
        run += v[j];
    }
}

__global__ void scan2(int* bsum, int n) {
    __shared__ int ts[512];
    int v = (threadIdx.x < n) ? bsum[threadIdx.x] : 0;
    ts[threadIdx.x] = v;
    __syncthreads();
    for (int off = 1; off < 512; off <<= 1) {
        int t = (threadIdx.x >= off) ? ts[threadIdx.x - off] : 0;
        __syncthreads();
        ts[threadIdx.x] += t;
        __syncthreads();
    }
    if (threadIdx.x < n) bsum[threadIdx.x] = ts[threadIdx.x] - v;
}

__global__ void scan3(int* out, const int* __restrict__ bsum) {
    int idx = blockIdx.x * blockDim.x + threadIdx.x;
    if (idx < SCAN_N) out[idx] += bsum[idx >> 11];
}

__global__ void scatter_k(const int* __restrict__ edge, int ne, const int* __restrict__ offs,
                          int* __restrict__ cur, int* __restrict__ sorted) {
    int i = blockIdx.x * blockDim.x + threadIdx.x;
    if (i < ne) {
        int s = edge[i], d = edge[ne + i];
        int pos = offs[d] + atomicAdd(&cur[d], 1);
        sorted[pos] = s;
    }
}

// ----------------- fused per-layer weight [k][o] + bias sum ------------------
__global__ void build_w(const float* __restrict__ sWl, const float* __restrict__ sWr,
                        const float* __restrict__ sb, float* __restrict__ Wb,
                        float* __restrict__ bS) {
    int i = blockIdx.x * blockDim.x + threadIdx.x;
    if (i >= 2 * 512 * HD) return;
    int l = i >> 16;
    int rem = i & 65535;
    int k = rem >> 7, o = rem & 127;
    float v;
    if (k < 384) {
        int part = k >> 7, kk = k & 127;
        v = sWl[(((size_t)(l * 3 + part)) * HD + o) * HD + kk];
    } else {
        int kk = k - 384;
        v = sWr[(((size_t)(l * 3 + 0)) * HD + o) * HD + kk] +
            sWr[(((size_t)(l * 3 + 1)) * HD + o) * HD + kk] +
            sWr[(((size_t)(l * 3 + 2)) * HD + o) * HD + kk];
    }
    Wb[i] = v;
    if (i < 2 * HD) {
        int l2 = i >> 7, o2 = i & 127;
        bS[i] = sb[(l2 * 3 + 0) * HD + o2] + sb[(l2 * 3 + 1) * HD + o2] +
                sb[(l2 * 3 + 2) * HD + o2];
    }
}

// --------------------------- feature encoders --------------------------------
__global__ __launch_bounds__(128) void enc_p(const float* __restrict__ xp,
                                             const float* __restrict__ embp,
                                             const float* __restrict__ Wp,
                                             const float* __restrict__ bp,
                                             float* __restrict__ out) {
    __shared__ float f[8][85];
    int r0 = blockIdx.x * 8;
    int tid = threadIdx.x;
    for (int idx = tid; idx < 8 * 85; idx += 128) {
        int r = idx / 85, k = idx - r * 85;
        const float* x = xp + (size_t)(r0 + r) * 10;
        float v;
        if (k < 5) {
            v = x[k == 0 ? 0 : k + 5];
        } else {
            int j = (k - 5) >> 4, e = (k - 5) & 15;
            int ci = (int)x[1 + j];
            ci = min(max(ci, 0), 199);
            v = embp[((size_t)j * 200 + ci) * 16 + e];
        }
        f[r][k] = v;
    }
    __syncthreads();
    float acc[8];
#pragma unroll
    for (int r = 0; r < 8; r++) acc[r] = bp[tid];
    const float* w = Wp + tid * 85;
    for (int k = 0; k < 85; k++) {
        float wk = __ldg(w + k);
#pragma unroll
        for (int r = 0; r < 8; r++) acc[r] += f[r][k] * wk;
    }
#pragma unroll
    for (int r = 0; r < 8; r++) out[(size_t)(r0 + r) * HD + tid] = acc[r];
}

__global__ __launch_bounds__(128) void enc_h(const float* __restrict__ xh,
                                             const float* __restrict__ e0,
                                             const float* __restrict__ e3,
                                             const float* __restrict__ Wh,
                                             const float* __restrict__ bh,
                                             float* __restrict__ out) {
    __shared__ float f[16][26];
    int r0 = blockIdx.x * 16;
    int tid = threadIdx.x;
    for (int idx = tid; idx < 16 * 26; idx += 128) {
        int r = idx / 26, k = idx - r * 26;
        const float* x = xh + (size_t)(r0 + r) * 8;
        float v;
        if (k < 6) {
            v = x[k < 2 ? k + 1 : k + 2];
        } else if (k < 22) {
            int ci = (int)x[0];
            ci = min(max(ci, 0), 1999);
            v = e0[ci * 16 + (k - 6)];
        } else {
            int ci = (int)x[3];
            ci = min(max(ci, 0), 9);
            v = e3[ci * 4 + (k - 22)];
        }
        f[r][k] = v;
    }
    __syncthreads();
    float acc[16];
#pragma unroll
    for (int r = 0; r < 16; r++) acc[r] = bh[tid];
    const float* w = Wh + tid * 26;
    for (int k = 0; k < 26; k++) {
        float wk = __ldg(w + k);
#pragma unroll
        for (int r = 0; r < 16; r++) acc[r] += f[r][k] * wk;
    }
#pragma unroll
    for (int r = 0; r < 16; r++) out[(size_t)(r0 + r) * HD + tid] = acc[r];
}

// ------------------------ CSR gather mean-aggregation ------------------------
// One warp per dst node: gather its neighbors' rows, average, write X slab.
__global__ __launch_bounds__(256) void agg_gather(const float* __restrict__ src, int srcStride,
                                                  const int* __restrict__ sorted,
                                                  const int* __restrict__ offs,
                                                  const int* __restrict__ cnt,
                                                  float* __restrict__ X, int outCol) {
    int w = (blockIdx.x * blockDim.x + threadIdx.x) >> 5;
    int lane = threadIdx.x & 31;
    if (w >= NP) return;
    int start = offs[w];
    int c = cnt[w];
    float4 acc = make_float4(0.f, 0.f, 0.f, 0.f);
    for (int e = 0; e < c; e++) {
        int s = sorted[start + e];
        float4 v = __ldg((const float4*)(src + (size_t)s * srcStride + lane * 4));
        acc.x += v.x; acc.y += v.y; acc.z += v.z; acc.w += v.w;
    }
    float inv = 1.0f / fmaxf((float)c, 1.0f);
    acc.x *= inv; acc.y *= inv; acc.z *= inv; acc.w *= inv;
    *(float4*)(X + (size_t)w * 384 + outCol + lane * 4) = acc;
}

// ------------------------------- tf32 MMA GEMM -------------------------------
__device__ __forceinline__ float f2tf(float x) {
    unsigned int u;
    asm("cvt.rna.tf32.f32 %0, %1;" : "=r"(u) : "f"(x));
    return __uint_as_float(u);
}

__device__ __forceinline__ void mma_tf32(float* c, const unsigned int* a, const unsigned int* b) {
    asm volatile(
        "mma.sync.aligned.m16n8k8.row.col.f32.tf32.tf32.f32 "
        "{%0,%1,%2,%3}, {%4,%5,%6,%7}, {%8,%9}, {%0,%1,%2,%3};"
        : "+f"(c[0]), "+f"(c[1]), "+f"(c[2]), "+f"(c[3])
        : "r"(a[0]), "r"(a[1]), "r"(a[2]), "r"(a[3]), "r"(b[0]), "r"(b[1]));
}

// C(128 rows x 128 cols per block) = relu([X | P](row,512) @ Wb(k,o) + bS)
__global__ __launch_bounds__(256) void sage_mma(const float* __restrict__ X,
                                                const float* __restrict__ P,
                                                const float* __restrict__ Wb,
                                                const float* __restrict__ bS,
                                                float* __restrict__ out, int ostride) {
    __shared__ float As[128][36];
    __shared__ float Bs[32][136];
    int tid = threadIdx.x, wid = tid >> 5, lane = tid & 31;
    int gr = lane >> 2, tg = lane & 3;
    int rowBase = blockIdx.x * 128;
    int wm = (wid >> 1) * 32, wn = (wid & 1) * 64;

    float acc[2][8][4];
#pragma unroll
    for (int i = 0; i < 2; i++)
#pragma unroll
        for (int j = 0; j < 8; j++)
#pragma unroll
            for (int k = 0; k < 4; k++) acc[i][j][k] = 0.f;

    for (int kc = 0; kc < 512; kc += 32) {
        // A tile: 128 rows x 32 k
#pragma unroll
        for (int t = 0; t < 4; t++) {
            int q = tid + t * 256;
            int r = q >> 3, c4 = (q & 7) * 4;
            int row = rowBase + r;
            if (row >= NP) row = NP - 1;
            const float* sp = (kc < 384) ? (X + (size_t)row * 384 + kc + c4)
                                         : (P + (size_t)row * 128 + (kc - 384) + c4);
            float4 v = *(const float4*)sp;
            As[r][c4 + 0] = f2tf(v.x);
            As[r][c4 + 1] = f2tf(v.y);
            As[r][c4 + 2] = f2tf(v.z);
            As[r][c4 + 3] = f2tf(v.w);
        }
        // B tile: 32 k x 128 o
#pragma unroll
        for (int t = 0; t < 4; t++) {
            int q = tid + t * 256;
            int kk = q >> 5, c4 = (q & 31) * 4;
            float4 v = *(const float4*)(Wb + (size_t)(kc + kk) * HD + c4);
            Bs[kk][c4 + 0] = f2tf(v.x);
            Bs[kk][c4 + 1] = f2tf(v.y);
            Bs[kk][c4 + 2] = f2tf(v.z);
            Bs[kk][c4 + 3] = f2tf(v.w);
        }
        __syncthreads();
#pragma unroll
        for (int ks = 0; ks < 4; ks++) {
            int k0 = ks * 8;
            unsigned int a[2][4];
#pragma unroll
            for (int mt = 0; mt < 2; mt++) {
                int r = wm + mt * 16;
                a[mt][0] = __float_as_uint(As[r + gr][k0 + tg]);
                a[mt][1] = __float_as_uint(As[r + gr + 8][k0 + tg]);
                a[mt][2] = __float_as_uint(As[r + gr][k0 + tg + 4]);
                a[mt][3] = __float_as_uint(As[r + gr + 8][k0 + tg + 4]);
            }
#pragma unroll
            for (int nt = 0; nt < 8; nt++) {
                unsigned int b[2];
                b[0] = __float_as_uint(Bs[k0 + tg][wn + nt * 8 + gr]);
                b[1] = __float_as_uint(Bs[k0 + tg + 4][wn + nt * 8 + gr]);
                mma_tf32(acc[0][nt], a[0], b);
                mma_tf32(acc[1][nt], a[1], b);
            }
        }
        __syncthreads();
    }
    // epilogue: bias + relu
#pragma unroll
    for (int mt = 0; mt < 2; mt++) {
#pragma unroll
        for (int nt = 0; nt < 8; nt++) {
            int col = wn + nt * 8 + 2 * tg;
            float b0 = bS[col], b1 = bS[col + 1];
            int r0 = rowBase + wm + mt * 16 + gr;
            if (r0 < NP) {
                float2 v;
                v.x = fmaxf(acc[mt][nt][0] + b0, 0.f);
                v.y = fmaxf(acc[mt][nt][1] + b1, 0.f);
                *(float2*)(out + (size_t)r0 * ostride + col) = v;
            }
            int r1 = r0 + 8;
            if (r1 < NP) {
                float2 v;
                v.x = fmaxf(acc[mt][nt][2] + b0, 0.f);
                v.y = fmaxf(acc[mt][nt][3] + b1, 0.f);
                *(float2*)(out + (size_t)r1 * ostride + col) = v;
            }
        }
    }
}

// ------------------------------ pooling/head ---------------------------------
__global__ __launch_bounds__(256) void pool_k(const float* __restrict__ P,
                                              const int* __restrict__ batch,
                                              const float* __restrict__ Wc,
                                              float* __restrict__ out, float* __restrict__ gc) {
    int row = (blockIdx.x * blockDim.x + threadIdx.x) >> 5;
    int lane = threadIdx.x & 31;
    if (row >= NP) return;
    const float4* pr = (const float4*)(P + (size_t)row * HD);
    const float4* wr = (const float4*)Wc;
    float4 a = pr[lane], b = wr[lane];
    float s = a.x * b.x + a.y * b.y + a.z * b.z + a.w * b.w;
#pragma unroll
    for (int o = 16; o; o >>= 1) s += __shfl_xor_sync(0xFFFFFFFFu, s, o);
    if (lane == 0) {
        int g = batch[row];
        atomicAdd(&out[g], s);
        atomicAdd(&gc[g], 1.0f);
    }
}

__global__ void fin_k(float* out, const float* gc, const float* __restrict__ bc) {
    int g = blockIdx.x * blockDim.x + threadIdx.x;
    if (g < NG) out[g] = out[g] / fmaxf(gc[g], 1.0f) + bc[0];
}

// -------------------------------- launcher -----------------------------------
extern "C" void kernel_launch(void* const* d_in, const int* in_sizes, int n_in,
                              void* d_out, int out_size) {
    const float* x_player = (const float*)d_in[0];
    const float* x_hist   = (const float*)d_in[1];
    const int*   e_t      = (const int*)d_in[2];
    const int*   e_e      = (const int*)d_in[3];
    const int*   e_h      = (const int*)d_in[4];
    const int*   batch    = (const int*)d_in[5];
    const float* emb_p    = (const float*)d_in[6];
    const float* emb_h0   = (const float*)d_in[7];
    const float* emb_h3   = (const float*)d_in[8];
    const float* Wp       = (const float*)d_in[9];
    const float* bp       = (const float*)d_in[10];
    const float* Wh       = (const float*)d_in[11];
    const float* bh       = (const float*)d_in[12];
    const float* sWl      = (const float*)d_in[13];
    const float* sb       = (const float*)d_in[14];
    const float* sWr      = (const float*)d_in[15];
    const float* Wc       = (const float*)d_in[16];
    const float* bc       = (const float*)d_in[17];
    float* out = (float*)d_out;

    float *P0, *P1, *Hf, *X, *Wb, *bS, *GC;
    int *cnt, *cur, *offs, *bsum, *sorted;
    cudaGetSymbolAddress((void**)&P0, g_P0);
    cudaGetSymbolAddress((void**)&P1, g_P1);
    cudaGetSymbolAddress((void**)&Hf, g_Hf);
    cudaGetSymbolAddress((void**)&X, g_X);
    cudaGetSymbolAddress((void**)&Wb, g_Wb);
    cudaGetSymbolAddress((void**)&bS, g_bSum);
    cudaGetSymbolAddress((void**)&GC, g_GC);
    cudaGetSymbolAddress((void**)&cnt, g_cnt);
    cudaGetSymbolAddress((void**)&cur, g_cur);
    cudaGetSymbolAddress((void**)&offs, g_offs);
    cudaGetSymbolAddress((void**)&bsum, g_bsum);
    cudaGetSymbolAddress((void**)&sorted, g_sorted);

    // ---- CSR build ----
    zero_buf<<<512, 256>>>((float*)cnt, SCAN_N);
    zero_buf<<<512, 256>>>((float*)cur, SCAN_N);
    counti_k<<<(NE_T + 255) / 256, 256>>>(e_t, NE_T, cnt);
    counti_k<<<(NE_E + 255) / 256, 256>>>(e_e, NE_E, cnt + NP);
    counti_k<<<(NE_H + 255) / 256, 256>>>(e_h, NE_H, cnt + 2 * NP);
    scan1<<<SCAN_BLOCKS, 256>>>(cnt, offs, bsum);
    scan2<<<1, 512>>>(bsum, SCAN_BLOCKS);
    scan3<<<(SCAN_N + 255) / 256, 256>>>(offs, bsum);
    scatter_k<<<(NE_T + 255) / 256, 256>>>(e_t, NE_T, offs, cur, sorted);
    scatter_k<<<(NE_E + 255) / 256, 256>>>(e_e, NE_E, offs + NP, cur + NP, sorted);
    scatter_k<<<(NE_H + 255) / 256, 256>>>(e_h, NE_H, offs + 2 * NP, cur + 2 * NP, sorted);

    // ---- weights + encoders ----
    build_w<<<(2 * 512 * HD + 255) / 256, 256>>>(sWl, sWr, sb, Wb, bS);
    enc_p<<<NP / 8, 128>>>(x_player, emb_p, Wp, bp, P0);
    enc_h<<<NH / 16, 128>>>(x_hist, emb_h0, emb_h3, Wh, bh, Hf);

    // ---- hist aggregation (layer-invariant) -> slab 2 ----
    agg_gather<<<NP / 8, 256>>>(Hf, HD, sorted, offs + 2 * NP, cnt + 2 * NP, X, 256);

    // ---- layer 0 ----
    agg_gather<<<NP / 8, 256>>>(P0, HD, sorted, offs, cnt, X, 0);
    agg_gather<<<NP / 8, 256>>>(P0, HD, sorted, offs + NP, cnt + NP, X, 128);
    sage_mma<<<(NP + 127) / 128, 256>>>(X, P0, Wb, bS, P1, HD);

    // ---- layer 1 ----
    agg_gather<<<NP / 8, 256>>>(P1, HD, sorted, offs, cnt, X, 0);
    agg_gather<<<NP / 8, 256>>>(P1, HD, sorted, offs + NP, cnt + NP, X, 128);
    sage_mma<<<(NP + 127) / 128, 256>>>(X, P1, Wb + 512 * HD, bS + HD, P0, HD);

    // ---- pooling + head ----
    zero_buf<<<(NG + 255) / 256, 256>>>(out, NG);
    zero_buf<<<(NG + 255) / 256, 256>>>(GC, NG);
    pool_k<<<NP * 32 / 256, 256>>>(P0, batch, Wc, out, GC);
    fin_k<<<(NG + 255) / 256, 256>>>(out, GC, bc);
}

// round 4
// speedup vs baseline: 3.5571x; 1.3471x over previous
#include <cuda_runtime.h>
#include <cuda_fp16.h>
#include <cstdint>

#define NP 200000
#define NH 500000
#define NG 20000
#define NE_T 800000
#define NE_E 1000000
#define NE_H 500000
#define NE_ALL (NE_T + NE_E + NE_H)
#define HD 128
#define SCAN_N (3 * NP)
#define SCAN_BLOCKS ((SCAN_N + 2047) / 2048)

// -------- static scratch (no allocations anywhere) --------
__device__ __half g_P0[(size_t)NP * HD];     // 51.2 MB
__device__ __half g_P1[(size_t)NP * HD];     // 51.2 MB
__device__ __half g_Hf[(size_t)NH * HD];     // 128 MB
__device__ __half g_X[(size_t)NP * 384];     // 153.6 MB [aggT | aggE | aggH]
__device__ __half g_Wbh[2 * HD * 512];       // fused weights [layer][o][k] fp16
__device__ float g_bSum[2 * HD];
__device__ float g_GC[NG];
__device__ int g_cnt[SCAN_N];
__device__ int g_cur[SCAN_N];
__device__ int g_offs[SCAN_N];
__device__ int g_bsum[SCAN_BLOCKS];
__device__ int g_sorted[NE_ALL];

// ------------------------------- utility ------------------------------------
__global__ void zero_buf(float* p, size_t n) {
    for (size_t i = (size_t)blockIdx.x * blockDim.x + threadIdx.x; i < n;
         i += (size_t)gridDim.x * blockDim.x)
        p[i] = 0.0f;
}

__global__ void counti_k(const int* __restrict__ edge, int ne, int* __restrict__ cnt) {
    int i = blockIdx.x * blockDim.x + threadIdx.x;
    if (i < ne) atomicAdd(&cnt[edge[ne + i]], 1);
}

// ------------------------------- scan (exclusive) ----------------------------
__global__ void scan1(const int* __restrict__ in, int* __restrict__ out, int* __restrict__ bsum) {
    __shared__ int ts[256];
    int base = blockIdx.x * 2048 + threadIdx.x * 8;
    int v[8];
    int s = 0;
#pragma unroll
    for (int j = 0; j < 8; j++) {
        int idx = base + j;
        v[j] = (idx < SCAN_N) ? in[idx] : 0;
        s += v[j];
    }
    ts[threadIdx.x] = s;
    __syncthreads();
    for (int off = 1; off < 256; off <<= 1) {
        int t = (threadIdx.x >= off) ? ts[threadIdx.x - off] : 0;
        __syncthreads();
        ts[threadIdx.x] += t;
        __syncthreads();
    }
    int run = ts[threadIdx.x] - s;  // exclusive
    if (threadIdx.x == 255) bsum[blockIdx.x] = ts[255];
#pragma unroll
    for (int j = 0; j < 8; j++) {
        int idx = base + j;
        if (idx < SCAN_N) out[idx] = run;
        run += v[j];
    }
}

__global__ void scan2(int* bsum, int n) {
    __shared__ int ts[512];
    int v = (threadIdx.x < n) ? bsum[threadIdx.x] : 0;
    ts[threadIdx.x] = v;
    __syncthreads();
    for (int off = 1; off < 512; off <<= 1) {
        int t = (threadIdx.x >= off) ? ts[threadIdx.x - off] : 0;
        __syncthreads();
        ts[threadIdx.x] += t;
        __syncthreads();
    }
    if (threadIdx.x < n) bsum[threadIdx.x] = ts[threadIdx.x] - v;
}

__global__ void scan3(int* out, const int* __restrict__ bsum) {
    int idx = blockIdx.x * blockDim.x + threadIdx.x;
    if (idx < SCAN_N) out[idx] += bsum[idx >> 11];
}

__global__ void scatter_k(const int* __restrict__ edge, int ne, const int* __restrict__ offs,
                          int* __restrict__ cur, int* __restrict__ sorted) {
    int i = blockIdx.x * blockDim.x + threadIdx.x;
    if (i < ne) {
        int s = edge[i], d = edge[ne + i];
        int pos = offs[d] + atomicAdd(&cur[d], 1);
        sorted[pos] = s;
    }
}

// ----------- fused per-layer weight [layer][o][k] fp16 + bias sum ------------
__global__ void build_w(const float* __restrict__ sWl, const float* __restrict__ sWr,
                        const float* __restrict__ sb, __half* __restrict__ Wbh,
                        float* __restrict__ bS) {
    int i = blockIdx.x * blockDim.x + threadIdx.x;
    if (i >= 2 * HD * 512) return;
    int l = i >> 16;       // 128*512 = 65536 per layer
    int rem = i & 65535;
    int o = rem >> 9;
    int k = rem & 511;
    float v;
    if (k < 384) {
        int part = k >> 7, kk = k & 127;
        v = sWl[(((size_t)(l * 3 + part)) * HD + o) * HD + kk];
    } else {
        int kk = k - 384;
        v = sWr[(((size_t)(l * 3 + 0)) * HD + o) * HD + kk] +
            sWr[(((size_t)(l * 3 + 1)) * HD + o) * HD + kk] +
            sWr[(((size_t)(l * 3 + 2)) * HD + o) * HD + kk];
    }
    Wbh[i] = __float2half(v);
    if (i < 2 * HD) {
        int l2 = i >> 7, o2 = i & 127;
        bS[i] = sb[(l2 * 3 + 0) * HD + o2] + sb[(l2 * 3 + 1) * HD + o2] +
                sb[(l2 * 3 + 2) * HD + o2];
    }
}

// --------------------------- feature encoders --------------------------------
__global__ __launch_bounds__(128) void enc_p(const float* __restrict__ xp,
                                             const float* __restrict__ embp,
                                             const float* __restrict__ Wp,
                                             const float* __restrict__ bp,
                                             __half* __restrict__ out) {
    __shared__ float f[8][85];
    int r0 = blockIdx.x * 8;
    int tid = threadIdx.x;
    for (int idx = tid; idx < 8 * 85; idx += 128) {
        int r = idx / 85, k = idx - r * 85;
        const float* x = xp + (size_t)(r0 + r) * 10;
        float v;
        if (k < 5) {
            v = x[k == 0 ? 0 : k + 5];
        } else {
            int j = (k - 5) >> 4, e = (k - 5) & 15;
            int ci = (int)x[1 + j];
            ci = min(max(ci, 0), 199);
            v = embp[((size_t)j * 200 + ci) * 16 + e];
        }
        f[r][k] = v;
    }
    __syncthreads();
    float acc[8];
#pragma unroll
    for (int r = 0; r < 8; r++) acc[r] = bp[tid];
    const float* w = Wp + tid * 85;
    for (int k = 0; k < 85; k++) {
        float wk = __ldg(w + k);
#pragma unroll
        for (int r = 0; r < 8; r++) acc[r] += f[r][k] * wk;
    }
#pragma unroll
    for (int r = 0; r < 8; r++) out[(size_t)(r0 + r) * HD + tid] = __float2half(acc[r]);
}

__global__ __launch_bounds__(128) void enc_h(const float* __restrict__ xh,
                                             const float* __restrict__ e0,
                                             const float* __restrict__ e3,
                                             const float* __restrict__ Wh,
                                             const float* __restrict__ bh,
                                             __half* __restrict__ out) {
    __shared__ float f[16][26];
    int r0 = blockIdx.x * 16;
    int tid = threadIdx.x;
    for (int idx = tid; idx < 16 * 26; idx += 128) {
        int r = idx / 26, k = idx - r * 26;
        const float* x = xh + (size_t)(r0 + r) * 8;
        float v;
        if (k < 6) {
            v = x[k < 2 ? k + 1 : k + 2];
        } else if (k < 22) {
            int ci = (int)x[0];
            ci = min(max(ci, 0), 1999);
            v = e0[ci * 16 + (k - 6)];
        } else {
            int ci = (int)x[3];
            ci = min(max(ci, 0), 9);
            v = e3[ci * 4 + (k - 22)];
        }
        f[r][k] = v;
    }
    __syncthreads();
    float acc[16];
#pragma unroll
    for (int r = 0; r < 16; r++) acc[r] = bh[tid];
    const float* w = Wh + tid * 26;
    for (int k = 0; k < 26; k++) {
        float wk = __ldg(w + k);
#pragma unroll
        for (int r = 0; r < 16; r++) acc[r] += f[r][k] * wk;
    }
#pragma unroll
    for (int r = 0; r < 16; r++) out[(size_t)(r0 + r) * HD + tid] = __float2half(acc[r]);
}

// ------------------------ CSR gather mean-aggregation ------------------------
// One warp per dst node: lane-parallel index fetch + shuffle; each lane owns
// 4 half columns (uint2 = 8B; warp covers the 256B fp16 row).
__global__ __launch_bounds__(256) void agg_gather(const __half* __restrict__ src,
                                                  const int* __restrict__ sorted,
                                                  const int* __restrict__ offs,
                                                  const int* __restrict__ cnt,
                                                  __half* __restrict__ X, int outCol) {
    int w = (blockIdx.x * blockDim.x + threadIdx.x) >> 5;
    int lane = threadIdx.x & 31;
    if (w >= NP) return;
    int start = offs[w];
    int c = cnt[w];
    float2 a0 = make_float2(0.f, 0.f), a1 = make_float2(0.f, 0.f);
    for (int e0 = 0; e0 < c; e0 += 32) {
        int my = (e0 + lane < c) ? sorted[start + e0 + lane] : 0;
        int n = min(32, c - e0);
        for (int e = 0; e < n; e++) {
            int s = __shfl_sync(0xFFFFFFFFu, my, e);
            uint2 v = __ldg((const uint2*)(src + (size_t)s * HD + lane * 4));
            float2 f0 = __half22float2(*(__half2*)&v.x);
            float2 f1 = __half22float2(*(__half2*)&v.y);
            a0.x += f0.x; a0.y += f0.y;
            a1.x += f1.x; a1.y += f1.y;
        }
    }
    float inv = 1.0f / fmaxf((float)c, 1.0f);
    __half2 o0 = __floats2half2_rn(a0.x * inv, a0.y * inv);
    __half2 o1 = __floats2half2_rn(a1.x * inv, a1.y * inv);
    uint2 ov;
    ov.x = *(unsigned int*)&o0;
    ov.y = *(unsigned int*)&o1;
    *(uint2*)(X + (size_t)w * 384 + outCol + lane * 4) = ov;
}

// ------------------------------- fp16 MMA GEMM -------------------------------
__device__ __forceinline__ void mma_f16(float* c, const unsigned int* a, const unsigned int* b) {
    asm volatile(
        "mma.sync.aligned.m16n8k16.row.col.f32.f16.f16.f32 "
        "{%0,%1,%2,%3}, {%4,%5,%6,%7}, {%8,%9}, {%0,%1,%2,%3};"
        : "+f"(c[0]), "+f"(c[1]), "+f"(c[2]), "+f"(c[3])
        : "r"(a[0]), "r"(a[1]), "r"(a[2]), "r"(a[3]), "r"(b[0]), "r"(b[1]));
}

// C(128 x 128 per block) = relu([X | P](row,512) @ Wbh[o][k].T + bS)
__global__ __launch_bounds__(256) void sage_mma(const __half* __restrict__ X,
                                                const __half* __restrict__ P,
                                                const __half* __restrict__ Wbh,
                                                const float* __restrict__ bS,
                                                __half* __restrict__ out) {
    __shared__ __half As[128][40];
    __shared__ __half Bs[128][40];
    int tid = threadIdx.x, wid = tid >> 5, lane = tid & 31;
    int gr = lane >> 2, tg = lane & 3;
    int rowBase = blockIdx.x * 128;
    int wm = (wid >> 1) * 32, wn = (wid & 1) * 64;

    float acc[2][8][4];
#pragma unroll
    for (int i = 0; i < 2; i++)
#pragma unroll
        for (int j = 0; j < 8; j++)
#pragma unroll
            for (int k = 0; k < 4; k++) acc[i][j][k] = 0.f;

    for (int kc = 0; kc < 512; kc += 32) {
        // A tile: 128 rows x 32 k halfs (uint4 = 8 halfs per thread, x2)
#pragma unroll
        for (int t = 0; t < 2; t++) {
            int q = tid + t * 256;
            int r = q >> 2, c8 = (q & 3) * 8;
            int row = min(rowBase + r, NP - 1);
            const __half* sp = (kc < 384) ? (X + (size_t)row * 384 + kc + c8)
                                          : (P + (size_t)row * HD + (kc - 384) + c8);
            *(uint4*)&As[r][c8] = *(const uint4*)sp;
        }
        // B tile: 128 o x 32 k halfs from Wbh[o][k]
#pragma unroll
        for (int t = 0; t < 2; t++) {
            int q = tid + t * 256;
            int o = q >> 2, c8 = (q & 3) * 8;
            *(uint4*)&Bs[o][c8] = *(const uint4*)(Wbh + (size_t)o * 512 + kc + c8);
        }
        __syncthreads();
#pragma unroll
        for (int ks = 0; ks < 2; ks++) {
            int k0 = ks * 16;
            unsigned int a[2][4];
#pragma unroll
            for (int mt = 0; mt < 2; mt++) {
                int r = wm + mt * 16 + gr;
                a[mt][0] = *(const unsigned int*)&As[r][k0 + 2 * tg];
                a[mt][1] = *(const unsigned int*)&As[r + 8][k0 + 2 * tg];
                a[mt][2] = *(const unsigned int*)&As[r][k0 + 2 * tg + 8];
                a[mt][3] = *(const unsigned int*)&As[r + 8][k0 + 2 * tg + 8];
            }
#pragma unroll
            for (int nt = 0; nt < 8; nt++) {
                int n = wn + nt * 8 + gr;
                unsigned int b[2];
                b[0] = *(const unsigned int*)&Bs[n][k0 + 2 * tg];
                b[1] = *(const unsigned int*)&Bs[n][k0 + 2 * tg + 8];
                mma_f16(acc[0][nt], a[0], b);
                mma_f16(acc[1][nt], a[1], b);
            }
        }
        __syncthreads();
    }
    // epilogue: bias + relu -> fp16
#pragma unroll
    for (int mt = 0; mt < 2; mt++) {
#pragma unroll
        for (int nt = 0; nt < 8; nt++) {
            int col = wn + nt * 8 + 2 * tg;
            float b0 = bS[col], b1 = bS[col + 1];
            int r0 = rowBase + wm + mt * 16 + gr;
            if (r0 < NP) {
                __half2 v = __floats2half2_rn(fmaxf(acc[mt][nt][0] + b0, 0.f),
                                              fmaxf(acc[mt][nt][1] + b1, 0.f));
                *(__half2*)(out + (size_t)r0 * HD + col) = v;
            }
            int r1 = r0 + 8;
            if (r1 < NP) {
                __half2 v = __floats2half2_rn(fmaxf(acc[mt][nt][2] + b0, 0.f),
                                              fmaxf(acc[mt][nt][3] + b1, 0.f));
                *(__half2*)(out + (size_t)r1 * HD + col) = v;
            }
        }
    }
}

// ------------------------------ pooling/head ---------------------------------
__global__ __launch_bounds__(256) void pool_k(const __half* __restrict__ P,
                                              const int* __restrict__ batch,
                                              const float* __restrict__ Wc,
                                              float* __restrict__ out, float* __restrict__ gc) {
    int row = (blockIdx.x * blockDim.x + threadIdx.x) >> 5;
    int lane = threadIdx.x & 31;
    if (row >= NP) return;
    uint2 v = __ldg((const uint2*)(P + (size_t)row * HD + lane * 4));
    float2 f0 = __half22float2(*(__half2*)&v.x);
    float2 f1 = __half22float2(*(__half2*)&v.y);
    float4 w = *(const float4*)(Wc + lane * 4);
    float s = f0.x * w.x + f0.y * w.y + f1.x * w.z + f1.y * w.w;
#pragma unroll
    for (int o = 16; o; o >>= 1) s += __shfl_xor_sync(0xFFFFFFFFu, s, o);
    if (lane == 0) {
        int g = batch[row];
        atomicAdd(&out[g], s);
        atomicAdd(&gc[g], 1.0f);
    }
}

__global__ void fin_k(float* out, const float* gc, const float* __restrict__ bc) {
    int g = blockIdx.x * blockDim.x + threadIdx.x;
    if (g < NG) out[g] = out[g] / fmaxf(gc[g], 1.0f) + bc[0];
}

// -------------------------------- launcher -----------------------------------
extern "C" void kernel_launch(void* const* d_in, const int* in_sizes, int n_in,
                              void* d_out, int out_size) {
    const float* x_player = (const float*)d_in[0];
    const float* x_hist   = (const float*)d_in[1];
    const int*   e_t      = (const int*)d_in[2];
    const int*   e_e      = (const int*)d_in[3];
    const int*   e_h      = (const int*)d_in[4];
    const int*   batch    = (const int*)d_in[5];
    const float* emb_p    = (const float*)d_in[6];
    const float* emb_h0   = (const float*)d_in[7];
    const float* emb_h3   = (const float*)d_in[8];
    const float* Wp       = (const float*)d_in[9];
    const float* bp       = (const float*)d_in[10];
    const float* Wh       = (const float*)d_in[11];
    const float* bh       = (const float*)d_in[12];
    const float* sWl      = (const float*)d_in[13];
    const float* sb       = (const float*)d_in[14];
    const float* sWr      = (const float*)d_in[15];
    const float* Wc       = (const float*)d_in[16];
    const float* bc       = (const float*)d_in[17];
    float* out = (float*)d_out;

    __half *P0, *P1, *Hf, *X, *Wbh;
    float *bS, *GC;
    int *cnt, *cur, *offs, *bsum, *sorted;
    cudaGetSymbolAddress((void**)&P0, g_P0);
    cudaGetSymbolAddress((void**)&P1, g_P1);
    cudaGetSymbolAddress((void**)&Hf, g_Hf);
    cudaGetSymbolAddress((void**)&X, g_X);
    cudaGetSymbolAddress((void**)&Wbh, g_Wbh);
    cudaGetSymbolAddress((void**)&bS, g_bSum);
    cudaGetSymbolAddress((void**)&GC, g_GC);
    cudaGetSymbolAddress((void**)&cnt, g_cnt);
    cudaGetSymbolAddress((void**)&cur, g_cur);
    cudaGetSymbolAddress((void**)&offs, g_offs);
    cudaGetSymbolAddress((void**)&bsum, g_bsum);
    cudaGetSymbolAddress((void**)&sorted, g_sorted);

    // ---- CSR build ----
    zero_buf<<<512, 256>>>((float*)cnt, SCAN_N);
    zero_buf<<<512, 256>>>((float*)cur, SCAN_N);
    counti_k<<<(NE_T + 255) / 256, 256>>>(e_t, NE_T, cnt);
    counti_k<<<(NE_E + 255) / 256, 256>>>(e_e, NE_E, cnt + NP);
    counti_k<<<(NE_H + 255) / 256, 256>>>(e_h, NE_H, cnt + 2 * NP);
    scan1<<<SCAN_BLOCKS, 256>>>(cnt, offs, bsum);
    scan2<<<1, 512>>>(bsum, SCAN_BLOCKS);
    scan3<<<(SCAN_N + 255) / 256, 256>>>(offs, bsum);
    scatter_k<<<(NE_T + 255) / 256, 256>>>(e_t, NE_T, offs, cur, sorted);
    scatter_k<<<(NE_E + 255) / 256, 256>>>(e_e, NE_E, offs + NP, cur + NP, sorted);
    scatter_k<<<(NE_H + 255) / 256, 256>>>(e_h, NE_H, offs + 2 * NP, cur + 2 * NP, sorted);

    // ---- weights + encoders ----
    build_w<<<(2 * HD * 512 + 255) / 256, 256>>>(sWl, sWr, sb, Wbh, bS);
    enc_p<<<NP / 8, 128>>>(x_player, emb_p, Wp, bp, P0);
    enc_h<<<NH / 16, 128>>>(x_hist, emb_h0, emb_h3, Wh, bh, Hf);

    // ---- hist aggregation (layer-invariant) -> slab 2 ----
    agg_gather<<<NP / 8, 256>>>(Hf, sorted, offs + 2 * NP, cnt + 2 * NP, X, 256);

    // ---- layer 0 ----
    agg_gather<<<NP / 8, 256>>>(P0, sorted, offs, cnt, X, 0);
    agg_gather<<<NP / 8, 256>>>(P0, sorted, offs + NP, cnt + NP, X, 128);
    sage_mma<<<(NP + 127) / 128, 256>>>(X, P0, Wbh, bS, P1);

    // ---- layer 1 ----
    agg_gather<<<NP / 8, 256>>>(P1, sorted, offs, cnt, X, 0);
    agg_gather<<<NP / 8, 256>>>(P1, sorted, offs + NP, cnt + NP, X, 128);
    sage_mma<<<(NP + 127) / 128, 256>>>(X, P1, Wbh + (size_t)HD * 512, bS + HD, P0);

    // ---- pooling + head ----
    zero_buf<<<(NG + 255) / 256, 256>>>(out, NG);
    zero_buf<<<(NG + 255) / 256, 256>>>(GC, NG);
    pool_k<<<NP * 32 / 256, 256>>>(P0, batch, Wc, out, GC);
    fin_k<<<(NG + 255) / 256, 256>>>(out, GC, bc);
}

// round 5
// speedup vs baseline: 4.5439x; 1.2774x over previous
#include <cuda_runtime.h>
#include <cuda_fp16.h>
#include <cstdint>

#define NP 200000
#define NH 500000
#define NG 20000
#define NE_T 800000
#define NE_E 1000000
#define NE_H 500000
#define NE_ALL (NE_T + NE_E + NE_H)
#define HD 128
#define XW 288              // X row: [aggT 128 | aggE 128 | aggH26 | flag | pad5]
#define KTOT 416            // 288 + 128 (P)
#define HCW 32              // Hcat padded row width (26 -> 32)
#define SCAN_N (3 * NP)
#define SCAN_BLOCKS ((SCAN_N + 2047) / 2048)

// -------- static scratch (no allocations anywhere) --------
__device__ __half g_P0[(size_t)NP * HD];     // 51.2 MB
__device__ __half g_P1[(size_t)NP * HD];     // 51.2 MB
__device__ __half g_Hc[(size_t)NH * HCW];    // 32 MB (raw hist concat, L2-resident)
__device__ __half g_X[(size_t)NP * XW];      // 115.2 MB
__device__ __half g_Wbh[2 * HD * KTOT];      // fused weights [layer][o][k(416)]
__device__ float g_bSum[2 * HD];
__device__ float g_GC[NG];
__device__ int g_cnt[SCAN_N];
__device__ int g_cur[SCAN_N];
__device__ int g_offs[SCAN_N];
__device__ int g_bsum[SCAN_BLOCKS];
__device__ int g_sorted[NE_ALL];

// ------------------------------- utility ------------------------------------
__global__ void zero_buf(float* p, size_t n) {
    for (size_t i = (size_t)blockIdx.x * blockDim.x + threadIdx.x; i < n;
         i += (size_t)gridDim.x * blockDim.x)
        p[i] = 0.0f;
}

__global__ void counti_k(const int* __restrict__ edge, int ne, int* __restrict__ cnt) {
    int i = blockIdx.x * blockDim.x + threadIdx.x;
    if (i < ne) atomicAdd(&cnt[edge[ne + i]], 1);
}

__global__ void gcount_k(const int* __restrict__ batch, float* __restrict__ gc) {
    int i = blockIdx.x * blockDim.x + threadIdx.x;
    if (i < NP) atomicAdd(&gc[batch[i]], 1.0f);
}

// ------------------------------- scan (exclusive) ----------------------------
__global__ void scan1(const int* __restrict__ in, int* __restrict__ out, int* __restrict__ bsum) {
    __shared__ int ts[256];
    int base = blockIdx.x * 2048 + threadIdx.x * 8;
    int v[8];
    int s = 0;
#pragma unroll
    for (int j = 0; j < 8; j++) {
        int idx = base + j;
        v[j] = (idx < SCAN_N) ? in[idx] : 0;
        s += v[j];
    }
    ts[threadIdx.x] = s;
    __syncthreads();
    for (int off = 1; off < 256; off <<= 1) {
        int t = (threadIdx.x >= off) ? ts[threadIdx.x - off] : 0;
        __syncthreads();
        ts[threadIdx.x] += t;
        __syncthreads();
    }
    int run = ts[threadIdx.x] - s;
    if (threadIdx.x == 255) bsum[blockIdx.x] = ts[255];
#pragma unroll
    for (int j = 0; j < 8; j++) {
        int idx = base + j;
        if (idx < SCAN_N) out[idx] = run;
        run += v[j];
    }
}

__global__ void scan2(int* bsum, int n) {
    __shared__ int ts[512];
    int v = (threadIdx.x < n) ? bsum[threadIdx.x] : 0;
    ts[threadIdx.x] = v;
    __syncthreads();
    for (int off = 1; off < 512; off <<= 1) {
        int t = (threadIdx.x >= off) ? ts[threadIdx.x - off] : 0;
        __syncthreads();
        ts[threadIdx.x] += t;
        __syncthreads();
    }
    if (threadIdx.x < n) bsum[threadIdx.x] = ts[threadIdx.x] - v;
}

__global__ void scan3(int* out, const int* __restrict__ bsum) {
    int idx = blockIdx.x * blockDim.x + threadIdx.x;
    if (idx < SCAN_N) out[idx] += bsum[idx >> 11];
}

__global__ void scatter_k(const int* __restrict__ edge, int ne, const int* __restrict__ offs,
                          int* __restrict__ cur, int* __restrict__ sorted) {
    int i = blockIdx.x * blockDim.x + threadIdx.x;
    if (i < ne) {
        int s = edge[i], d = edge[ne + i];
        int pos = offs[d] + atomicAdd(&cur[d], 1);
        sorted[pos] = s;
    }
}

// ------ fused per-layer weight [layer][o][k(416)] with hist-encoder fold -----
// k<128: Wl_t | 128..255: Wl_e | 256..281: Wl_h@Wh | 282: Wl_h@bh | 283..287:0
// 288..415: Wr0+Wr1+Wr2
__global__ void build_w(const float* __restrict__ sWl, const float* __restrict__ sWr,
                        const float* __restrict__ sb, const float* __restrict__ Wh,
                        const float* __restrict__ bh, __half* __restrict__ Wbh,
                        float* __restrict__ bS) {
    int i = blockIdx.x * blockDim.x + threadIdx.x;
    if (i >= 2 * HD * KTOT) return;
    int l = i / (HD * KTOT);
    int rem = i - l * HD * KTOT;
    int o = rem / KTOT;
    int k = rem - o * KTOT;
    float v;
    if (k < 256) {
        int part = k >> 7, kk = k & 127;
        v = sWl[(((size_t)(l * 3 + part)) * HD + o) * HD + kk];
    } else if (k < 282) {
        int c = k - 256;
        float s = 0.f;
        const float* wl = sWl + ((size_t)(l * 3 + 2) * HD + o) * HD;
        for (int j = 0; j < HD; j++) s += wl[j] * Wh[j * 26 + c];
        v = s;
    } else if (k == 282) {
        float s = 0.f;
        const float* wl = sWl + ((size_t)(l * 3 + 2) * HD + o) * HD;
        for (int j = 0; j < HD; j++) s += wl[j] * bh[j];
        v = s;
    } else if (k < 288) {
        v = 0.f;
    } else {
        int kk = k - 288;
        v = sWr[(((size_t)(l * 3 + 0)) * HD + o) * HD + kk] +
            sWr[(((size_t)(l * 3 + 1)) * HD + o) * HD + kk] +
            sWr[(((size_t)(l * 3 + 2)) * HD + o) * HD + kk];
    }
    Wbh[i] = __float2half(v);
    if (i < 2 * HD) {
        int l2 = i >> 7, o2 = i & 127;
        bS[i] = sb[(l2 * 3 + 0) * HD + o2] + sb[(l2 * 3 + 1) * HD + o2] +
                sb[(l2 * 3 + 2) * HD + o2];
    }
}

// --------------------------- player encoder ----------------------------------
__global__ __launch_bounds__(128) void enc_p(const float* __restrict__ xp,
                                             const float* __restrict__ embp,
                                             const float* __restrict__ Wp,
                                             const float* __restrict__ bp,
                                             __half* __restrict__ out) {
    __shared__ float f[8][85];
    int r0 = blockIdx.x * 8;
    int tid = threadIdx.x;
    for (int idx = tid; idx < 8 * 85; idx += 128) {
        int r = idx / 85, k = idx - r * 85;
        const float* x = xp + (size_t)(r0 + r) * 10;
        float v;
        if (k < 5) {
            v = x[k == 0 ? 0 : k + 5];
        } else {
            int j = (k - 5) >> 4, e = (k - 5) & 15;
            int ci = (int)x[1 + j];
            ci = min(max(ci, 0), 199);
            v = embp[((size_t)j * 200 + ci) * 16 + e];
        }
        f[r][k] = v;
    }
    __syncthreads();
    float acc[8];
#pragma unroll
    for (int r = 0; r < 8; r++) acc[r] = bp[tid];
    const float* w = Wp + tid * 85;
    for (int k = 0; k < 85; k++) {
        float wk = __ldg(w + k);
#pragma unroll
        for (int r = 0; r < 8; r++) acc[r] += f[r][k] * wk;
    }
#pragma unroll
    for (int r = 0; r < 8; r++) out[(size_t)(r0 + r) * HD + tid] = __float2half(acc[r]);
}

// -------------- raw hist concat (26 dims, padded to 32 halfs) ----------------
__global__ __launch_bounds__(256) void build_hcat(const float* __restrict__ xh,
                                                  const float* __restrict__ e0,
                                                  const float* __restrict__ e3,
                                                  __half* __restrict__ Hc) {
    int r = blockIdx.x * blockDim.x + threadIdx.x;
    if (r >= NH) return;
    const float* x = xh + (size_t)r * 8;
    float f[32];
    f[0] = x[1]; f[1] = x[2]; f[2] = x[4]; f[3] = x[5]; f[4] = x[6]; f[5] = x[7];
    int c0 = min(max((int)x[0], 0), 1999);
    int c3 = min(max((int)x[3], 0), 9);
#pragma unroll
    for (int j = 0; j < 16; j++) f[6 + j] = e0[c0 * 16 + j];
#pragma unroll
    for (int j = 0; j < 4; j++) f[22 + j] = e3[c3 * 4 + j];
#pragma unroll
    for (int j = 26; j < 32; j++) f[j] = 0.f;
    __half h[32];
#pragma unroll
    for (int j = 0; j < 32; j++) h[j] = __float2half(f[j]);
#pragma unroll
    for (int q = 0; q < 4; q++)
        *(uint4*)(Hc + (size_t)r * HCW + q * 8) = *(uint4*)&h[q * 8];
}

// ---------------- fused teammate+enemy gather (MLP-4 unrolled) ---------------
__device__ __forceinline__ float4 gather_mean128(const __half* __restrict__ src,
                                                 const int* __restrict__ sorted,
                                                 int start, int c, int lane) {
    float4 a = make_float4(0.f, 0.f, 0.f, 0.f);
    for (int e0 = 0; e0 < c; e0 += 32) {
        int my = (e0 + lane < c) ? sorted[start + e0 + lane] : 0;
        int n = min(32, c - e0);
        int e = 0;
        for (; e + 4 <= n; e += 4) {
            int s0 = __shfl_sync(0xFFFFFFFFu, my, e);
            int s1 = __shfl_sync(0xFFFFFFFFu, my, e + 1);
            int s2 = __shfl_sync(0xFFFFFFFFu, my, e + 2);
            int s3 = __shfl_sync(0xFFFFFFFFu, my, e + 3);
            uint2 v0 = __ldg((const uint2*)(src + (size_t)s0 * HD + lane * 4));
            uint2 v1 = __ldg((const uint2*)(src + (size_t)s1 * HD + lane * 4));
            uint2 v2 = __ldg((const uint2*)(src + (size_t)s2 * HD + lane * 4));
            uint2 v3 = __ldg((const uint2*)(src + (size_t)s3 * HD + lane * 4));
            float2 f;
            f = __half22float2(*(__half2*)&v0.x); a.x += f.x; a.y += f.y;
            f = __half22float2(*(__half2*)&v0.y); a.z += f.x; a.w += f.y;
            f = __half22float2(*(__half2*)&v1.x); a.x += f.x; a.y += f.y;
            f = __half22float2(*(__half2*)&v1.y); a.z += f.x; a.w += f.y;
            f = __half22float2(*(__half2*)&v2.x); a.x += f.x; a.y += f.y;
            f = __half22float2(*(__half2*)&v2.y); a.z += f.x; a.w += f.y;
            f = __half22float2(*(__half2*)&v3.x); a.x += f.x; a.y += f.y;
            f = __half22float2(*(__half2*)&v3.y); a.z += f.x; a.w += f.y;
        }
        for (; e < n; e++) {
            int s = __shfl_sync(0xFFFFFFFFu, my, e);
            uint2 v = __ldg((const uint2*)(src + (size_t)s * HD + lane * 4));
            float2 f;
            f = __half22float2(*(__half2*)&v.x); a.x += f.x; a.y += f.y;
            f = __half22float2(*(__half2*)&v.y); a.z += f.x; a.w += f.y;
        }
    }
    return a;
}

__global__ __launch_bounds__(256) void agg_te(const __half* __restrict__ P,
                                              const int* __restrict__ sorted,
                                              const int* __restrict__ offs,
                                              const int* __restrict__ cnt,
                                              __half* __restrict__ X) {
    int w = (blockIdx.x * blockDim.x + threadIdx.x) >> 5;
    int lane = threadIdx.x & 31;
    if (w >= NP) return;
    // teammate
    {
        int start = offs[w], c = cnt[w];
        float4 a = gather_mean128(P, sorted, start, c, lane);
        float inv = 1.0f / fmaxf((float)c, 1.0f);
        __half2 o0 = __floats2half2_rn(a.x * inv, a.y * inv);
        __half2 o1 = __floats2half2_rn(a.z * inv, a.w * inv);
        uint2 ov; ov.x = *(unsigned int*)&o0; ov.y = *(unsigned int*)&o1;
        *(uint2*)(X + (size_t)w * XW + lane * 4) = ov;
    }
    // enemy
    {
        int start = offs[NP + w], c = cnt[NP + w];
        float4 a = gather_mean128(P, sorted, start, c, lane);
        float inv = 1.0f / fmaxf((float)c, 1.0f);
        __half2 o0 = __floats2half2_rn(a.x * inv, a.y * inv);
        __half2 o1 = __floats2half2_rn(a.z * inv, a.w * inv);
        uint2 ov; ov.x = *(unsigned int*)&o0; ov.y = *(unsigned int*)&o1;
        *(uint2*)(X + (size_t)w * XW + 128 + lane * 4) = ov;
    }
}

// ------------- hist gather: half-warp per node over 32-half rows -------------
__global__ __launch_bounds__(256) void agg_h(const __half* __restrict__ Hc,
                                             const int* __restrict__ sorted,
                                             const int* __restrict__ offs,
                                             const int* __restrict__ cnt,
                                             __half* __restrict__ X) {
    int hw = (blockIdx.x * blockDim.x + threadIdx.x) >> 4;  // half-warp id = node
    int lane = threadIdx.x & 15;
    if (hw >= NP) return;
    int start = offs[hw], c = cnt[hw];
    float2 a = make_float2(0.f, 0.f);
    for (int e = 0; e < c; e++) {
        int s = __ldg(sorted + start + e);
        unsigned int v = __ldg((const unsigned int*)(Hc + (size_t)s * HCW + lane * 2));
        float2 f = __half22float2(*(__half2*)&v);
        a.x += f.x; a.y += f.y;
    }
    float inv = 1.0f / fmaxf((float)c, 1.0f);
    int col = lane * 2;  // 0..30 within hist slab
    float v0 = a.x * inv, v1 = a.y * inv;
    if (col == 26) { v0 = (c > 0) ? 1.f : 0.f; v1 = 0.f; }  // flag at 282
    else if (col > 26) { v0 = 0.f; v1 = 0.f; }
    __half2 o = __floats2half2_rn(v0, v1);
    *(__half2*)(X + (size_t)hw * XW + 256 + col) = o;
}

// ------------------------------- fp16 MMA GEMM -------------------------------
__device__ __forceinline__ void mma_f16(float* c, const unsigned int* a, const unsigned int* b) {
    asm volatile(
        "mma.sync.aligned.m16n8k16.row.col.f32.f16.f16.f32 "
        "{%0,%1,%2,%3}, {%4,%5,%6,%7}, {%8,%9}, {%0,%1,%2,%3};"
        : "+f"(c[0]), "+f"(c[1]), "+f"(c[2]), "+f"(c[3])
        : "r"(a[0]), "r"(a[1]), "r"(a[2]), "r"(a[3]), "r"(b[0]), "r"(b[1]));
}

// C(128x128 per block) = relu([X | P](row,416) @ Wbh[o][k].T + bS)
// do_pool: instead of writing C, compute dot(C_row, Wc) and atomicAdd per graph.
__global__ __launch_bounds__(256) void sage_mma(const __half* __restrict__ X,
                                                const __half* __restrict__ P,
                                                const __half* __restrict__ Wbh,
                                                const float* __restrict__ bS,
                                                __half* __restrict__ out,
                                                const int* __restrict__ batch,
                                                const float* __restrict__ Wc,
                                                float* __restrict__ pool_out,
                                                int do_pool) {
    __shared__ __half As[128][40];
    __shared__ __half Bs[128][40];
    int tid = threadIdx.x, wid = tid >> 5, lane = tid & 31;
    int gr = lane >> 2, tg = lane & 3;
    int rowBase = blockIdx.x * 128;
    int wm = (wid >> 1) * 32, wn = (wid & 1) * 64;

    float acc[2][8][4];
#pragma unroll
    for (int i = 0; i < 2; i++)
#pragma unroll
        for (int j = 0; j < 8; j++)
#pragma unroll
            for (int k = 0; k < 4; k++) acc[i][j][k] = 0.f;

    for (int kc = 0; kc < KTOT; kc += 32) {
#pragma unroll
        for (int t = 0; t < 2; t++) {
            int q = tid + t * 256;
            int r = q >> 2, c8 = (q & 3) * 8;
            int row = min(rowBase + r, NP - 1);
            const __half* sp = (kc < XW) ? (X + (size_t)row * XW + kc + c8)
                                         : (P + (size_t)row * HD + (kc - XW) + c8);
            *(uint4*)&As[r][c8] = *(const uint4*)sp;
        }
#pragma unroll
        for (int t = 0; t < 2; t++) {
            int q = tid + t * 256;
            int o = q >> 2, c8 = (q & 3) * 8;
            *(uint4*)&Bs[o][c8] = *(const uint4*)(Wbh + (size_t)o * KTOT + kc + c8);
        }
        __syncthreads();
#pragma unroll
        for (int ks = 0; ks < 2; ks++) {
            int k0 = ks * 16;
            unsigned int a[2][4];
#pragma unroll
            for (int mt = 0; mt < 2; mt++) {
                int r = wm + mt * 16 + gr;
                a[mt][0] = *(const unsigned int*)&As[r][k0 + 2 * tg];
                a[mt][1] = *(const unsigned int*)&As[r + 8][k0 + 2 * tg];
                a[mt][2] = *(const unsigned int*)&As[r][k0 + 2 * tg + 8];
                a[mt][3] = *(const unsigned int*)&As[r + 8][k0 + 2 * tg + 8];
            }
#pragma unroll
            for (int nt = 0; nt < 8; nt++) {
                int n = wn + nt * 8 + gr;
                unsigned int b[2];
                b[0] = *(const unsigned int*)&Bs[n][k0 + 2 * tg];
                b[1] = *(const unsigned int*)&Bs[n][k0 + 2 * tg + 8];
                mma_f16(acc[0][nt], a[0], b);
                mma_f16(acc[1][nt], a[1], b);
            }
        }
        __syncthreads();
    }

    if (do_pool) {
        float ps[4] = {0.f, 0.f, 0.f, 0.f};
#pragma unroll
        for (int mt = 0; mt < 2; mt++)
#pragma unroll
            for (int nt = 0; nt < 8; nt++) {
                int col = wn + nt * 8 + 2 * tg;
                float w0 = Wc[col], w1 = Wc[col + 1];
                float b0 = bS[col], b1 = bS[col + 1];
                ps[mt * 2 + 0] += fmaxf(acc[mt][nt][0] + b0, 0.f) * w0 +
                                  fmaxf(acc[mt][nt][1] + b1, 0.f) * w1;
                ps[mt * 2 + 1] += fmaxf(acc[mt][nt][2] + b0, 0.f) * w0 +
                                  fmaxf(acc[mt][nt][3] + b1, 0.f) * w1;
            }
#pragma unroll
        for (int j = 0; j < 4; j++) {
            ps[j] += __shfl_xor_sync(0xFFFFFFFFu, ps[j], 1);
            ps[j] += __shfl_xor_sync(0xFFFFFFFFu, ps[j], 2);
        }
        if (tg == 0) {
#pragma unroll
            for (int mt = 0; mt < 2; mt++) {
                int r0 = rowBase + wm + mt * 16 + gr;
                int r1 = r0 + 8;
                if (r0 < NP) atomicAdd(&pool_out[batch[r0]], ps[mt * 2]);
                if (r1 < NP) atomicAdd(&pool_out[batch[r1]], ps[mt * 2 + 1]);
            }
        }
    } else {
#pragma unroll
        for (int mt = 0; mt < 2; mt++) {
#pragma unroll
            for (int nt = 0; nt < 8; nt++) {
                int col = wn + nt * 8 + 2 * tg;
                float b0 = bS[col], b1 = bS[col + 1];
                int r0 = rowBase + wm + mt * 16 + gr;
                if (r0 < NP) {
                    __half2 v = __floats2half2_rn(fmaxf(acc[mt][nt][0] + b0, 0.f),
                                                  fmaxf(acc[mt][nt][1] + b1, 0.f));
                    *(__half2*)(out + (size_t)r0 * HD + col) = v;
                }
                int r1 = r0 + 8;
                if (r1 < NP) {
                    __half2 v = __floats2half2_rn(fmaxf(acc[mt][nt][2] + b0, 0.f),
                                                  fmaxf(acc[mt][nt][3] + b1, 0.f));
                    *(__half2*)(out + (size_t)r1 * HD + col) = v;
                }
            }
        }
    }
}

__global__ void fin_k(float* out, const float* gc, const float* __restrict__ bc) {
    int g = blockIdx.x * blockDim.x + threadIdx.x;
    if (g < NG) out[g] = out[g] / fmaxf(gc[g], 1.0f) + bc[0];
}

// -------------------------------- launcher -----------------------------------
extern "C" void kernel_launch(void* const* d_in, const int* in_sizes, int n_in,
                              void* d_out, int out_size) {
    const float* x_player = (const float*)d_in[0];
    const float* x_hist   = (const float*)d_in[1];
    const int*   e_t      = (const int*)d_in[2];
    const int*   e_e      = (const int*)d_in[3];
    const int*   e_h      = (const int*)d_in[4];
    const int*   batch    = (const int*)d_in[5];
    const float* emb_p    = (const float*)d_in[6];
    const float* emb_h0   = (const float*)d_in[7];
    const float* emb_h3   = (const float*)d_in[8];
    const float* Wp       = (const float*)d_in[9];
    const float* bp       = (const float*)d_in[10];
    const float* Wh       = (const float*)d_in[11];
    const float* bh       = (const float*)d_in[12];
    const float* sWl      = (const float*)d_in[13];
    const float* sb       = (const float*)d_in[14];
    const float* sWr      = (const float*)d_in[15];
    const float* Wc       = (const float*)d_in[16];
    const float* bc       = (const float*)d_in[17];
    float* out = (float*)d_out;

    __half *P0, *P1, *Hc, *X, *Wbh;
    float *bS, *GC;
    int *cnt, *cur, *offs, *bsum, *sorted;
    cudaGetSymbolAddress((void**)&P0, g_P0);
    cudaGetSymbolAddress((void**)&P1, g_P1);
    cudaGetSymbolAddress((void**)&Hc, g_Hc);
    cudaGetSymbolAddress((void**)&X, g_X);
    cudaGetSymbolAddress((void**)&Wbh, g_Wbh);
    cudaGetSymbolAddress((void**)&bS, g_bSum);
    cudaGetSymbolAddress((void**)&GC, g_GC);
    cudaGetSymbolAddress((void**)&cnt, g_cnt);
    cudaGetSymbolAddress((void**)&cur, g_cur);
    cudaGetSymbolAddress((void**)&offs, g_offs);
    cudaGetSymbolAddress((void**)&bsum, g_bsum);
    cudaGetSymbolAddress((void**)&sorted, g_sorted);

    // ---- CSR build ----
    zero_buf<<<512, 256>>>((float*)cnt, SCAN_N);
    zero_buf<<<512, 256>>>((float*)cur, SCAN_N);
    counti_k<<<(NE_T + 255) / 256, 256>>>(e_t, NE_T, cnt);
    counti_k<<<(NE_E + 255) / 256, 256>>>(e_e, NE_E, cnt + NP);
    counti_k<<<(NE_H + 255) / 256, 256>>>(e_h, NE_H, cnt + 2 * NP);
    scan1<<<SCAN_BLOCKS, 256>>>(cnt, offs, bsum);
    scan2<<<1, 512>>>(bsum, SCAN_BLOCKS);
    scan3<<<(SCAN_N + 255) / 256, 256>>>(offs, bsum);
    scatter_k<<<(NE_T + 255) / 256, 256>>>(e_t, NE_T, offs, cur, sorted);
    scatter_k<<<(NE_E + 255) / 256, 256>>>(e_e, NE_E, offs + NP, cur + NP, sorted);
    scatter_k<<<(NE_H + 255) / 256, 256>>>(e_h, NE_H, offs + 2 * NP, cur + 2 * NP, sorted);

    // ---- weights + encoders ----
    build_w<<<(2 * HD * KTOT + 255) / 256, 256>>>(sWl, sWr, sb, Wh, bh, Wbh, bS);
    enc_p<<<NP / 8, 128>>>(x_player, emb_p, Wp, bp, P0);
    build_hcat<<<(NH + 255) / 256, 256>>>(x_hist, emb_h0, emb_h3, Hc);

    // ---- hist aggregation (layer-invariant, 26-dim raw) ----
    agg_h<<<NP / 16, 256>>>(Hc, sorted, offs + 2 * NP, cnt + 2 * NP, X);

    // ---- layer 0 ----
    agg_te<<<NP / 8, 256>>>(P0, sorted, offs, cnt, X);
    sage_mma<<<(NP + 127) / 128, 256>>>(X, P0, Wbh, bS, P1, batch, Wc, out, 0);

    // ---- layer 1 (pool fused into epilogue) ----
    zero_buf<<<(NG + 255) / 256, 256>>>(out, NG);
    zero_buf<<<(NG + 255) / 256, 256>>>(GC, NG);
    gcount_k<<<(NP + 255) / 256, 256>>>(batch, GC);
    agg_te<<<NP / 8, 256>>>(P1, sorted, offs, cnt, X);
    sage_mma<<<(NP + 127) / 128, 256>>>(X, P1, Wbh + (size_t)HD * KTOT, bS + HD, P0,
                                        batch, Wc, out, 1);

    fin_k<<<(NG + 255) / 256, 256>>>(out, GC, bc);
}